// round 3
// baseline (speedup 1.0000x reference)
#include <cuda_runtime.h>
#include <cstdint>

// DKVMN: B=64, T=100, DK=DV=N=128, NUM_Q=1000
// out = [ p (6400) | Mv (6400*128*128) ] fp32

// -------- scratch (static device globals; no allocation) --------
__device__ float g_Wp[1000 * 128];      // softmax(k_emb @ Mk)
__device__ float g_Gp[1000 * 128];      // k_emb @ f_W[128:] + f_b
__device__ float g_Ep[2000 * 128];      // sigmoid(v_emb @ e_W + e_b)
__device__ float g_Ap[2000 * 128];      // tanh(v_emb @ a_W + a_b)
__device__ float g_R[6400 * 8 * 128];   // rt partials per n-chunk

// ============================================================
// Phase A: build lookup tables. grid 96 x 128 threads.
//   blocks 0..15  : W_pre  (k_emb, Mk, softmax)     1000 rows
//   blocks 16..31 : G_pre  (k_emb, f_W+16384, +f_b) 1000 rows
//   blocks 32..63 : E_pre  (v_emb, e_W, sigmoid)    2000 rows
//   blocks 64..95 : A_pre  (v_emb, a_W, tanh)       2000 rows
// ============================================================
__global__ void kA(const float* __restrict__ k_emb, const float* __restrict__ v_emb,
                   const float* __restrict__ Mk, const float* __restrict__ f_W,
                   const float* __restrict__ f_b, const float* __restrict__ e_W,
                   const float* __restrict__ e_b, const float* __restrict__ a_W,
                   const float* __restrict__ a_b) {
    extern __shared__ float sm[];
    float* Xs = sm;          // 64*128
    float* Wb = sm + 8192;   // 128*128
    const int bid = blockIdx.x, tid = threadIdx.x;

    const float* Xsrc; const float* Wsrc; const float* bias; float* dst;
    int rowbase, nrows, mode;  // 0 softmax, 1 +bias, 2 sigmoid, 3 tanh
    if (bid < 16)      { Xsrc = k_emb; Wsrc = Mk;          bias = f_b; dst = g_Wp; rowbase = bid * 64;        nrows = 1000; mode = 0; }
    else if (bid < 32) { Xsrc = k_emb; Wsrc = f_W + 16384; bias = f_b; dst = g_Gp; rowbase = (bid - 16) * 64; nrows = 1000; mode = 1; }
    else if (bid < 64) { Xsrc = v_emb; Wsrc = e_W;         bias = e_b; dst = g_Ep; rowbase = (bid - 32) * 64; nrows = 2000; mode = 2; }
    else               { Xsrc = v_emb; Wsrc = a_W;         bias = a_b; dst = g_Ap; rowbase = (bid - 64) * 64; nrows = 2000; mode = 3; }

    // load 64 X rows (clamped) + weight 128x128 into smem
    for (int i = tid; i < 2048; i += 128) {
        int rloc = i >> 5, seg = i & 31;
        int row = rowbase + rloc; if (row >= nrows) row = nrows - 1;
        *(float4*)(Xs + rloc * 128 + seg * 4) =
            *(const float4*)(Xsrc + (size_t)row * 128 + seg * 4);
    }
    for (int i = tid; i < 4096; i += 128)
        ((float4*)Wb)[i] = ((const float4*)Wsrc)[i];
    __syncthreads();

    const int bg = tid >> 4, nq = tid & 15;   // 8 rows x 8 cols per thread
    float acc[8][8];
#pragma unroll
    for (int bb = 0; bb < 8; bb++)
#pragma unroll
        for (int jj = 0; jj < 8; jj++) acc[bb][jj] = 0.f;

    for (int k = 0; k < 128; k++) {
        float4 w0 = *(float4*)(Wb + k * 128 + nq * 8);
        float4 w1 = *(float4*)(Wb + k * 128 + nq * 8 + 4);
#pragma unroll
        for (int bb = 0; bb < 8; bb++) {
            float x = Xs[(bg * 8 + bb) * 128 + k];
            acc[bb][0] = fmaf(x, w0.x, acc[bb][0]); acc[bb][1] = fmaf(x, w0.y, acc[bb][1]);
            acc[bb][2] = fmaf(x, w0.z, acc[bb][2]); acc[bb][3] = fmaf(x, w0.w, acc[bb][3]);
            acc[bb][4] = fmaf(x, w1.x, acc[bb][4]); acc[bb][5] = fmaf(x, w1.y, acc[bb][5]);
            acc[bb][6] = fmaf(x, w1.z, acc[bb][6]); acc[bb][7] = fmaf(x, w1.w, acc[bb][7]);
        }
    }

    float bia[8];
#pragma unroll
    for (int jj = 0; jj < 8; jj++) bia[jj] = bias[nq * 8 + jj];

#pragma unroll
    for (int bb = 0; bb < 8; bb++) {
        int row = rowbase + bg * 8 + bb;
        float v[8];
        if (mode == 0) {
            float mx = acc[bb][0];
#pragma unroll
            for (int jj = 1; jj < 8; jj++) mx = fmaxf(mx, acc[bb][jj]);
#pragma unroll
            for (int o = 8; o; o >>= 1) mx = fmaxf(mx, __shfl_xor_sync(0xffffffffu, mx, o));
            float s = 0.f;
#pragma unroll
            for (int jj = 0; jj < 8; jj++) { v[jj] = __expf(acc[bb][jj] - mx); s += v[jj]; }
#pragma unroll
            for (int o = 8; o; o >>= 1) s += __shfl_xor_sync(0xffffffffu, s, o);
            float inv = 1.f / s;
#pragma unroll
            for (int jj = 0; jj < 8; jj++) v[jj] *= inv;
        } else if (mode == 1) {
#pragma unroll
            for (int jj = 0; jj < 8; jj++) v[jj] = acc[bb][jj] + bia[jj];
        } else if (mode == 2) {
#pragma unroll
            for (int jj = 0; jj < 8; jj++) v[jj] = 1.f / (1.f + __expf(-(acc[bb][jj] + bia[jj])));
        } else {
#pragma unroll
            for (int jj = 0; jj < 8; jj++) v[jj] = tanhf(acc[bb][jj] + bia[jj]);
        }
        if (row < nrows) {
            *(float4*)(dst + (size_t)row * 128 + nq * 8)     = make_float4(v[0], v[1], v[2], v[3]);
            *(float4*)(dst + (size_t)row * 128 + nq * 8 + 4) = make_float4(v[4], v[5], v[6], v[7]);
        }
    }
}

// ============================================================
// Phase B: memory recurrence + Mv trajectory + rt partials.
// grid 512 = 64 b x 8 n-chunks, 128 threads.
// Thread owns 4 n x 4 d (d-major float4) in registers.
// ============================================================
__global__ void kB(const int* __restrict__ q, const int* __restrict__ r,
                   const float* __restrict__ Mv0, float* __restrict__ outMv) {
    __shared__ float sbuf[2 * 512];
    const int blk = blockIdx.x;
    const int b = blk >> 3, chunk = blk & 7;
    const int tid = threadIdx.x;
    const int d4 = tid & 31, ng = tid >> 5;      // warp = one n-group of 4
    const int nbase = chunk * 16 + ng * 4;

    float4 M0 = *(const float4*)(Mv0 + (nbase + 0) * 128 + d4 * 4);
    float4 M1 = *(const float4*)(Mv0 + (nbase + 1) * 128 + d4 * 4);
    float4 M2 = *(const float4*)(Mv0 + (nbase + 2) * 128 + d4 * 4);
    float4 M3 = *(const float4*)(Mv0 + (nbase + 3) * 128 + d4 * 4);

    const int* qb = q + b * 100;
    const int* rb = r + b * 100;

    for (int t = 0; t < 100; t++) {
        const int qv = qb[t];
        const int qr = qv + 1000 * rb[t];
        float4 wv = *(const float4*)(g_Wp + (size_t)qv * 128 + nbase);
        float4 ev = *(const float4*)(g_Ep + (size_t)qr * 128 + d4 * 4);
        float4 av = *(const float4*)(g_Ap + (size_t)qr * 128 + d4 * 4);

        // rt partial from PRE-update M
        float4 P;
        P.x = fmaf(wv.x, M0.x, fmaf(wv.y, M1.x, fmaf(wv.z, M2.x, wv.w * M3.x)));
        P.y = fmaf(wv.x, M0.y, fmaf(wv.y, M1.y, fmaf(wv.z, M2.y, wv.w * M3.y)));
        P.z = fmaf(wv.x, M0.z, fmaf(wv.y, M1.z, fmaf(wv.z, M2.z, wv.w * M3.z)));
        P.w = fmaf(wv.x, M0.w, fmaf(wv.y, M1.w, fmaf(wv.z, M2.w, wv.w * M3.w)));

        // update: M += w * (a - M*e)   (== M*(1-w*e) + w*a)
#define UPD(MM, WI) { \
        float ux = fmaf(-(MM).x, ev.x, av.x); (MM).x = fmaf((WI), ux, (MM).x); \
        float uy = fmaf(-(MM).y, ev.y, av.y); (MM).y = fmaf((WI), uy, (MM).y); \
        float uz = fmaf(-(MM).z, ev.z, av.z); (MM).z = fmaf((WI), uz, (MM).z); \
        float uw = fmaf(-(MM).w, ev.w, av.w); (MM).w = fmaf((WI), uw, (MM).w); }
        UPD(M0, wv.x); UPD(M1, wv.y); UPD(M2, wv.z); UPD(M3, wv.w);
#undef UPD

        const size_t rowb = (size_t)(t * 64 + b);
        float* o = outMv + (rowb * 128 + nbase) * 128 + d4 * 4;
        *(float4*)(o)       = M0;
        *(float4*)(o + 128) = M1;
        *(float4*)(o + 256) = M2;
        *(float4*)(o + 384) = M3;

        // cross-warp reduce of rt partials (double-buffered -> 1 bar/step)
        const int off = (t & 1) << 9;
        *(float4*)(sbuf + off + ng * 128 + d4 * 4) = P;
        __syncthreads();
        float rs = sbuf[off + tid] + sbuf[off + 128 + tid] +
                   sbuf[off + 256 + tid] + sbuf[off + 384 + tid];
        g_R[(rowb * 8 + chunk) * 128 + tid] = rs;
    }
}

// ============================================================
// Phase C: reduce rt partials, ft = tanh(rt@f_W1 + G), p = sigmoid(ft.p_W + p_b)
// grid 100 (one t) x 128 threads.
// ============================================================
__global__ void kC(const int* __restrict__ q, const float* __restrict__ f_W,
                   const float* __restrict__ p_W, const float* __restrict__ p_b,
                   float* __restrict__ outP) {
    extern __shared__ float smc[];
    float* rts = smc;         // 64*128
    float* Ws  = smc + 8192;  // 128*128 (f_W rows 0..127)
    const int t = blockIdx.x, tid = threadIdx.x;

    for (int i = tid; i < 8192; i += 128) {
        int b = i >> 7, d = i & 127;
        const float* rp = g_R + ((size_t)(t * 64 + b) * 8) * 128 + d;
        float s = rp[0];
#pragma unroll
        for (int c = 1; c < 8; c++) s += rp[c * 128];
        rts[i] = s;
    }
    for (int i = tid; i < 4096; i += 128)
        ((float4*)Ws)[i] = ((const float4*)f_W)[i];
    __syncthreads();

    const int bg = tid >> 4, nq = tid & 15;
    float acc[8][8];
#pragma unroll
    for (int bb = 0; bb < 8; bb++)
#pragma unroll
        for (int jj = 0; jj < 8; jj++) acc[bb][jj] = 0.f;

    for (int k = 0; k < 128; k++) {
        float4 w0 = *(float4*)(Ws + k * 128 + nq * 8);
        float4 w1 = *(float4*)(Ws + k * 128 + nq * 8 + 4);
#pragma unroll
        for (int bb = 0; bb < 8; bb++) {
            float x = rts[(bg * 8 + bb) * 128 + k];
            acc[bb][0] = fmaf(x, w0.x, acc[bb][0]); acc[bb][1] = fmaf(x, w0.y, acc[bb][1]);
            acc[bb][2] = fmaf(x, w0.z, acc[bb][2]); acc[bb][3] = fmaf(x, w0.w, acc[bb][3]);
            acc[bb][4] = fmaf(x, w1.x, acc[bb][4]); acc[bb][5] = fmaf(x, w1.y, acc[bb][5]);
            acc[bb][6] = fmaf(x, w1.z, acc[bb][6]); acc[bb][7] = fmaf(x, w1.w, acc[bb][7]);
        }
    }

    float pw[8];
#pragma unroll
    for (int jj = 0; jj < 8; jj++) pw[jj] = p_W[nq * 8 + jj];
    const float pb = p_b[0];

#pragma unroll
    for (int bb = 0; bb < 8; bb++) {
        int b = bg * 8 + bb;
        int qv = q[b * 100 + t];
        const float* Gr = g_Gp + (size_t)qv * 128 + nq * 8;
        float dot = 0.f;
#pragma unroll
        for (int jj = 0; jj < 8; jj++) {
            float h = acc[bb][jj] + Gr[jj];
            dot = fmaf(tanhf(h), pw[jj], dot);
        }
#pragma unroll
        for (int o = 8; o; o >>= 1) dot += __shfl_xor_sync(0xffffffffu, dot, o);
        if (nq == 0) outP[t * 64 + b] = 1.f / (1.f + __expf(-(dot + pb)));
    }
}

// ============================================================
extern "C" void kernel_launch(void* const* d_in, const int* in_sizes, int n_in,
                              void* d_out, int out_size) {
    const int*   q     = (const int*)d_in[0];
    const int*   r     = (const int*)d_in[1];
    const float* k_emb = (const float*)d_in[2];
    const float* v_emb = (const float*)d_in[3];
    const float* Mk    = (const float*)d_in[4];
    const float* Mv0   = (const float*)d_in[5];
    const float* f_W   = (const float*)d_in[6];
    const float* f_b   = (const float*)d_in[7];
    const float* p_W   = (const float*)d_in[8];
    const float* p_b   = (const float*)d_in[9];
    const float* e_W   = (const float*)d_in[10];
    const float* e_b   = (const float*)d_in[11];
    const float* a_W   = (const float*)d_in[12];
    const float* a_b   = (const float*)d_in[13];
    float* out = (float*)d_out;

    cudaFuncSetAttribute(kA, cudaFuncAttributeMaxDynamicSharedMemorySize, 98304);
    cudaFuncSetAttribute(kC, cudaFuncAttributeMaxDynamicSharedMemorySize, 98304);

    kA<<<96, 128, 98304>>>(k_emb, v_emb, Mk, f_W, f_b, e_W, e_b, a_W, a_b);
    kB<<<512, 128>>>(q, r, Mv0, out + 6400);
    kC<<<100, 128, 98304>>>(q, f_W, p_W, p_b, out);
}

// round 4
// speedup vs baseline: 1.2377x; 1.2377x over previous
#include <cuda_runtime.h>
#include <cstdint>

// DKVMN: B=64, T=100, DK=DV=N=128, NUM_Q=1000
// out = [ p (6400) | Mv (6400*128*128) ] fp32

// -------- scratch (static device globals; no allocation) --------
__device__ float g_Wp[1000 * 128];      // softmax(k_emb @ Mk)
__device__ float g_Gp[1000 * 128];      // k_emb @ f_W[128:] + f_b
__device__ float g_Ep[2000 * 128];      // sigmoid(v_emb @ e_W + e_b)
__device__ float g_Ap[2000 * 128];      // tanh(v_emb @ a_W + a_b)
__device__ float g_R[6400 * 8 * 128];   // rt partials per n-chunk

// ============================================================
// Phase A: build lookup tables. grid 96 x 512 threads.
// Each block: 64 X-rows x 128 cols. Warp owns 4 rows; lane owns 4 cols.
//   blocks 0..15  : W_pre  (k_emb, Mk, softmax)     1000 rows
//   blocks 16..31 : G_pre  (k_emb, f_W[128:], +f_b) 1000 rows
//   blocks 32..63 : E_pre  (v_emb, e_W, sigmoid)    2000 rows
//   blocks 64..95 : A_pre  (v_emb, a_W, tanh)       2000 rows
// ============================================================
__global__ void kA(const float* __restrict__ k_emb, const float* __restrict__ v_emb,
                   const float* __restrict__ Mk, const float* __restrict__ f_W,
                   const float* __restrict__ f_b, const float* __restrict__ e_W,
                   const float* __restrict__ e_b, const float* __restrict__ a_W,
                   const float* __restrict__ a_b) {
    extern __shared__ float sm[];
    float* Xs = sm;          // 64*128 = 32KB
    float* Wb = sm + 8192;   // 128*128 = 64KB
    const int bid = blockIdx.x, tid = threadIdx.x;

    const float* Xsrc; const float* Wsrc; const float* bias; float* dst;
    int rowbase, nrows, mode;  // 0 softmax, 1 +bias, 2 sigmoid, 3 tanh
    if (bid < 16)      { Xsrc = k_emb; Wsrc = Mk;          bias = f_b; dst = g_Wp; rowbase = bid * 64;        nrows = 1000; mode = 0; }
    else if (bid < 32) { Xsrc = k_emb; Wsrc = f_W + 16384; bias = f_b; dst = g_Gp; rowbase = (bid - 16) * 64; nrows = 1000; mode = 1; }
    else if (bid < 64) { Xsrc = v_emb; Wsrc = e_W;         bias = e_b; dst = g_Ep; rowbase = (bid - 32) * 64; nrows = 2000; mode = 2; }
    else               { Xsrc = v_emb; Wsrc = a_W;         bias = a_b; dst = g_Ap; rowbase = (bid - 64) * 64; nrows = 2000; mode = 3; }

    // stage 64 X rows (clamped) + 128x128 weight into smem
    for (int i = tid; i < 2048; i += 512) {
        int rloc = i >> 5, seg = i & 31;
        int row = rowbase + rloc; if (row >= nrows) row = nrows - 1;
        *(float4*)(Xs + rloc * 128 + seg * 4) =
            *(const float4*)(Xsrc + (size_t)row * 128 + seg * 4);
    }
    for (int i = tid; i < 4096; i += 512)
        ((float4*)Wb)[i] = ((const float4*)Wsrc)[i];
    __syncthreads();

    const int wid = tid >> 5, lane = tid & 31;   // warp -> 4 rows, lane -> 4 cols
    float acc[4][4];
#pragma unroll
    for (int rr = 0; rr < 4; rr++)
#pragma unroll
        for (int jj = 0; jj < 4; jj++) acc[rr][jj] = 0.f;

    const float* xrow = Xs + (wid * 4) * 128;
#pragma unroll 4
    for (int k = 0; k < 128; k++) {
        float4 w = *(float4*)(Wb + k * 128 + lane * 4);
        float x0 = xrow[k], x1 = xrow[128 + k], x2 = xrow[256 + k], x3 = xrow[384 + k];
        acc[0][0] = fmaf(x0, w.x, acc[0][0]); acc[0][1] = fmaf(x0, w.y, acc[0][1]);
        acc[0][2] = fmaf(x0, w.z, acc[0][2]); acc[0][3] = fmaf(x0, w.w, acc[0][3]);
        acc[1][0] = fmaf(x1, w.x, acc[1][0]); acc[1][1] = fmaf(x1, w.y, acc[1][1]);
        acc[1][2] = fmaf(x1, w.z, acc[1][2]); acc[1][3] = fmaf(x1, w.w, acc[1][3]);
        acc[2][0] = fmaf(x2, w.x, acc[2][0]); acc[2][1] = fmaf(x2, w.y, acc[2][1]);
        acc[2][2] = fmaf(x2, w.z, acc[2][2]); acc[2][3] = fmaf(x2, w.w, acc[2][3]);
        acc[3][0] = fmaf(x3, w.x, acc[3][0]); acc[3][1] = fmaf(x3, w.y, acc[3][1]);
        acc[3][2] = fmaf(x3, w.z, acc[3][2]); acc[3][3] = fmaf(x3, w.w, acc[3][3]);
    }

    float bia[4];
#pragma unroll
    for (int jj = 0; jj < 4; jj++) bia[jj] = bias[lane * 4 + jj];

#pragma unroll
    for (int rr = 0; rr < 4; rr++) {
        int row = rowbase + wid * 4 + rr;
        float v[4];
        if (mode == 0) {
            float mx = fmaxf(fmaxf(acc[rr][0], acc[rr][1]), fmaxf(acc[rr][2], acc[rr][3]));
#pragma unroll
            for (int o = 16; o; o >>= 1) mx = fmaxf(mx, __shfl_xor_sync(0xffffffffu, mx, o));
            float s = 0.f;
#pragma unroll
            for (int jj = 0; jj < 4; jj++) { v[jj] = __expf(acc[rr][jj] - mx); s += v[jj]; }
#pragma unroll
            for (int o = 16; o; o >>= 1) s += __shfl_xor_sync(0xffffffffu, s, o);
            float inv = 1.f / s;
#pragma unroll
            for (int jj = 0; jj < 4; jj++) v[jj] *= inv;
        } else if (mode == 1) {
#pragma unroll
            for (int jj = 0; jj < 4; jj++) v[jj] = acc[rr][jj] + bia[jj];
        } else if (mode == 2) {
#pragma unroll
            for (int jj = 0; jj < 4; jj++) v[jj] = 1.f / (1.f + __expf(-(acc[rr][jj] + bia[jj])));
        } else {
#pragma unroll
            for (int jj = 0; jj < 4; jj++) v[jj] = tanhf(acc[rr][jj] + bia[jj]);
        }
        if (row < nrows)
            *(float4*)(dst + (size_t)row * 128 + lane * 4) = make_float4(v[0], v[1], v[2], v[3]);
    }
}

// ============================================================
// Phase B: memory recurrence + Mv trajectory + rt partials.
// grid 512 = 64 b x 8 n-chunks, 128 threads.
// Thread owns 4 n x 4 d (d-major float4) in registers.
// Software-pipelined table prefetch; q/r staged in smem.
// ============================================================
__global__ void kB(const int* __restrict__ q, const int* __restrict__ r,
                   const float* __restrict__ Mv0, float* __restrict__ outMv) {
    __shared__ float sbuf[2 * 512];
    __shared__ int sq[100], sr[100];
    const int blk = blockIdx.x;
    const int b = blk >> 3, chunk = blk & 7;
    const int tid = threadIdx.x;
    const int d4 = tid & 31, ng = tid >> 5;      // warp = one n-group of 4
    const int nbase = chunk * 16 + ng * 4;

    for (int i = tid; i < 100; i += 128) { sq[i] = q[b * 100 + i]; sr[i] = r[b * 100 + i]; }

    float4 M0 = *(const float4*)(Mv0 + (nbase + 0) * 128 + d4 * 4);
    float4 M1 = *(const float4*)(Mv0 + (nbase + 1) * 128 + d4 * 4);
    float4 M2 = *(const float4*)(Mv0 + (nbase + 2) * 128 + d4 * 4);
    float4 M3 = *(const float4*)(Mv0 + (nbase + 3) * 128 + d4 * 4);
    __syncthreads();

    int qv = sq[0];
    int qr = qv + 1000 * sr[0];
    float4 wv = *(const float4*)(g_Wp + (size_t)qv * 128 + nbase);
    float4 ev = *(const float4*)(g_Ep + (size_t)qr * 128 + d4 * 4);
    float4 av = *(const float4*)(g_Ap + (size_t)qr * 128 + d4 * 4);

    for (int t = 0; t < 100; t++) {
        // prefetch next step's table rows (independent of this step's compute)
        float4 wv2 = wv, ev2 = ev, av2 = av;
        if (t < 99) {
            int qv2 = sq[t + 1];
            int qr2 = qv2 + 1000 * sr[t + 1];
            wv2 = *(const float4*)(g_Wp + (size_t)qv2 * 128 + nbase);
            ev2 = *(const float4*)(g_Ep + (size_t)qr2 * 128 + d4 * 4);
            av2 = *(const float4*)(g_Ap + (size_t)qr2 * 128 + d4 * 4);
        }

        // rt partial from PRE-update M
        float4 P;
        P.x = fmaf(wv.x, M0.x, fmaf(wv.y, M1.x, fmaf(wv.z, M2.x, wv.w * M3.x)));
        P.y = fmaf(wv.x, M0.y, fmaf(wv.y, M1.y, fmaf(wv.z, M2.y, wv.w * M3.y)));
        P.z = fmaf(wv.x, M0.z, fmaf(wv.y, M1.z, fmaf(wv.z, M2.z, wv.w * M3.z)));
        P.w = fmaf(wv.x, M0.w, fmaf(wv.y, M1.w, fmaf(wv.z, M2.w, wv.w * M3.w)));

        // publish partial early so the barrier isn't gated on the update math
        const int off = (t & 1) << 9;
        *(float4*)(sbuf + off + ng * 128 + d4 * 4) = P;

        // update: M += w * (a - M*e)   (== M*(1-w*e) + w*a)
#define UPD(MM, WI) { \
        float ux = fmaf(-(MM).x, ev.x, av.x); (MM).x = fmaf((WI), ux, (MM).x); \
        float uy = fmaf(-(MM).y, ev.y, av.y); (MM).y = fmaf((WI), uy, (MM).y); \
        float uz = fmaf(-(MM).z, ev.z, av.z); (MM).z = fmaf((WI), uz, (MM).z); \
        float uw = fmaf(-(MM).w, ev.w, av.w); (MM).w = fmaf((WI), uw, (MM).w); }
        UPD(M0, wv.x); UPD(M1, wv.y); UPD(M2, wv.z); UPD(M3, wv.w);
#undef UPD
        __syncthreads();

        const size_t rowb = (size_t)(t * 64 + b);
        float* o = outMv + (rowb * 128 + nbase) * 128 + d4 * 4;
        *(float4*)(o)       = M0;
        *(float4*)(o + 128) = M1;
        *(float4*)(o + 256) = M2;
        *(float4*)(o + 384) = M3;

        float rs = sbuf[off + tid] + sbuf[off + 128 + tid] +
                   sbuf[off + 256 + tid] + sbuf[off + 384 + tid];
        g_R[(rowb * 8 + chunk) * 128 + tid] = rs;

        wv = wv2; ev = ev2; av = av2;
    }
}

// ============================================================
// Phase C: reduce rt partials, ft = tanh(rt@f_W0 + G), p = sigmoid(ft.p_W + p_b)
// grid 100 (one t) x 512 threads. Warp owns 4 b-rows; lane owns 4 cols.
// ============================================================
__global__ void kC(const int* __restrict__ q, const float* __restrict__ f_W,
                   const float* __restrict__ p_W, const float* __restrict__ p_b,
                   float* __restrict__ outP) {
    extern __shared__ float smc[];
    float* rts = smc;         // 64*128
    float* Ws  = smc + 8192;  // 128*128 (f_W rows 0..127)
    const int t = blockIdx.x, tid = threadIdx.x;

    for (int i = tid; i < 8192; i += 512) {
        int b = i >> 7, d = i & 127;
        const float* rp = g_R + ((size_t)(t * 64 + b) * 8) * 128 + d;
        float s = rp[0];
#pragma unroll
        for (int c = 1; c < 8; c++) s += rp[c * 128];
        rts[i] = s;
    }
    for (int i = tid; i < 4096; i += 512)
        ((float4*)Ws)[i] = ((const float4*)f_W)[i];
    __syncthreads();

    const int wid = tid >> 5, lane = tid & 31;
    float acc[4][4];
#pragma unroll
    for (int rr = 0; rr < 4; rr++)
#pragma unroll
        for (int jj = 0; jj < 4; jj++) acc[rr][jj] = 0.f;

    const float* xrow = rts + (wid * 4) * 128;
#pragma unroll 4
    for (int k = 0; k < 128; k++) {
        float4 w = *(float4*)(Ws + k * 128 + lane * 4);
        float x0 = xrow[k], x1 = xrow[128 + k], x2 = xrow[256 + k], x3 = xrow[384 + k];
        acc[0][0] = fmaf(x0, w.x, acc[0][0]); acc[0][1] = fmaf(x0, w.y, acc[0][1]);
        acc[0][2] = fmaf(x0, w.z, acc[0][2]); acc[0][3] = fmaf(x0, w.w, acc[0][3]);
        acc[1][0] = fmaf(x1, w.x, acc[1][0]); acc[1][1] = fmaf(x1, w.y, acc[1][1]);
        acc[1][2] = fmaf(x1, w.z, acc[1][2]); acc[1][3] = fmaf(x1, w.w, acc[1][3]);
        acc[2][0] = fmaf(x2, w.x, acc[2][0]); acc[2][1] = fmaf(x2, w.y, acc[2][1]);
        acc[2][2] = fmaf(x2, w.z, acc[2][2]); acc[2][3] = fmaf(x2, w.w, acc[2][3]);
        acc[3][0] = fmaf(x3, w.x, acc[3][0]); acc[3][1] = fmaf(x3, w.y, acc[3][1]);
        acc[3][2] = fmaf(x3, w.z, acc[3][2]); acc[3][3] = fmaf(x3, w.w, acc[3][3]);
    }

    float pw[4];
#pragma unroll
    for (int jj = 0; jj < 4; jj++) pw[jj] = p_W[lane * 4 + jj];
    const float pb = p_b[0];

#pragma unroll
    for (int rr = 0; rr < 4; rr++) {
        int b = wid * 4 + rr;
        int qv = q[b * 100 + t];
        const float* Gr = g_Gp + (size_t)qv * 128 + lane * 4;
        float dot = 0.f;
#pragma unroll
        for (int jj = 0; jj < 4; jj++) {
            float h = acc[rr][jj] + Gr[jj];
            dot = fmaf(tanhf(h), pw[jj], dot);
        }
#pragma unroll
        for (int o = 16; o; o >>= 1) dot += __shfl_xor_sync(0xffffffffu, dot, o);
        if (lane == 0) outP[t * 64 + b] = 1.f / (1.f + __expf(-(dot + pb)));
    }
}

// ============================================================
extern "C" void kernel_launch(void* const* d_in, const int* in_sizes, int n_in,
                              void* d_out, int out_size) {
    const int*   q     = (const int*)d_in[0];
    const int*   r     = (const int*)d_in[1];
    const float* k_emb = (const float*)d_in[2];
    const float* v_emb = (const float*)d_in[3];
    const float* Mk    = (const float*)d_in[4];
    const float* Mv0   = (const float*)d_in[5];
    const float* f_W   = (const float*)d_in[6];
    const float* f_b   = (const float*)d_in[7];
    const float* p_W   = (const float*)d_in[8];
    const float* p_b   = (const float*)d_in[9];
    const float* e_W   = (const float*)d_in[10];
    const float* e_b   = (const float*)d_in[11];
    const float* a_W   = (const float*)d_in[12];
    const float* a_b   = (const float*)d_in[13];
    float* out = (float*)d_out;

    cudaFuncSetAttribute(kA, cudaFuncAttributeMaxDynamicSharedMemorySize, 98304);
    cudaFuncSetAttribute(kC, cudaFuncAttributeMaxDynamicSharedMemorySize, 98304);

    kA<<<96, 512, 98304>>>(k_emb, v_emb, Mk, f_W, f_b, e_W, e_b, a_W, a_b);
    kB<<<512, 128>>>(q, r, Mv0, out + 6400);
    kC<<<100, 512, 98304>>>(q, f_W, p_W, p_b, out);
}

// round 8
// speedup vs baseline: 1.2918x; 1.0437x over previous
#include <cuda_runtime.h>
#include <cstdint>

// DKVMN: B=64, T=100, DK=DV=N=128, NUM_Q=1000
// out = [ p (6400) | Mv (6400*128*128) ] fp32

// -------- scratch (static device globals; no allocation) --------
__device__ float g_Wp[1000 * 128];      // softmax(k_emb @ Mk)
__device__ float g_Gp[1000 * 128];      // k_emb @ f_W[128:] + f_b
__device__ float g_Ep[2000 * 128];      // sigmoid(v_emb @ e_W + e_b)
__device__ float g_Ap[2000 * 128];      // tanh(v_emb @ a_W + a_b)
__device__ float g_R[6400 * 8 * 128];   // rt partials per n-chunk

// ============================================================
// Phase A: build lookup tables. grid 190 x 256 threads.
// Each block: 32 X-rows x 128 cols (80KB smem -> 2 blocks/SM).
// Warp owns 4 rows; lane owns 4 cols.
//   blocks   0..31  : W_pre  (k_emb, Mk, softmax)     1000 rows
//   blocks  32..63  : G_pre  (k_emb, f_W[128:], +f_b) 1000 rows
//   blocks  64..126 : E_pre  (v_emb, e_W, sigmoid)    2000 rows
//   blocks 127..189 : A_pre  (v_emb, a_W, tanh)       2000 rows
// ============================================================
__global__ void kA(const float* __restrict__ k_emb, const float* __restrict__ v_emb,
                   const float* __restrict__ Mk, const float* __restrict__ f_W,
                   const float* __restrict__ f_b, const float* __restrict__ e_W,
                   const float* __restrict__ e_b, const float* __restrict__ a_W,
                   const float* __restrict__ a_b) {
    extern __shared__ float sm[];
    float* Xs = sm;          // 32*128 = 16KB
    float* Wb = sm + 4096;   // 128*128 = 64KB
    const int bid = blockIdx.x, tid = threadIdx.x;

    const float* Xsrc; const float* Wsrc; const float* bias; float* dst;
    int rowbase, nrows, mode;  // 0 softmax, 1 +bias, 2 sigmoid, 3 tanh
    if (bid < 32)       { Xsrc = k_emb; Wsrc = Mk;          bias = f_b; dst = g_Wp; rowbase = bid * 32;         nrows = 1000; mode = 0; }
    else if (bid < 64)  { Xsrc = k_emb; Wsrc = f_W + 16384; bias = f_b; dst = g_Gp; rowbase = (bid - 32) * 32;  nrows = 1000; mode = 1; }
    else if (bid < 127) { Xsrc = v_emb; Wsrc = e_W;         bias = e_b; dst = g_Ep; rowbase = (bid - 64) * 32;  nrows = 2000; mode = 2; }
    else                { Xsrc = v_emb; Wsrc = a_W;         bias = a_b; dst = g_Ap; rowbase = (bid - 127) * 32; nrows = 2000; mode = 3; }

    // stage 32 X rows (clamped) + 128x128 weight into smem
    for (int i = tid; i < 1024; i += 256) {
        int rloc = i >> 5, seg = i & 31;
        int row = rowbase + rloc; if (row >= nrows) row = nrows - 1;
        *(float4*)(Xs + rloc * 128 + seg * 4) =
            *(const float4*)(Xsrc + (size_t)row * 128 + seg * 4);
    }
    for (int i = tid; i < 4096; i += 256)
        ((float4*)Wb)[i] = ((const float4*)Wsrc)[i];
    __syncthreads();

    const int wid = tid >> 5, lane = tid & 31;   // warp -> 4 rows, lane -> 4 cols
    float acc[4][4];
#pragma unroll
    for (int rr = 0; rr < 4; rr++)
#pragma unroll
        for (int jj = 0; jj < 4; jj++) acc[rr][jj] = 0.f;

    const float* xrow = Xs + (wid * 4) * 128;
#pragma unroll 4
    for (int k = 0; k < 128; k++) {
        float4 w = *(float4*)(Wb + k * 128 + lane * 4);
        float x0 = xrow[k], x1 = xrow[128 + k], x2 = xrow[256 + k], x3 = xrow[384 + k];
        acc[0][0] = fmaf(x0, w.x, acc[0][0]); acc[0][1] = fmaf(x0, w.y, acc[0][1]);
        acc[0][2] = fmaf(x0, w.z, acc[0][2]); acc[0][3] = fmaf(x0, w.w, acc[0][3]);
        acc[1][0] = fmaf(x1, w.x, acc[1][0]); acc[1][1] = fmaf(x1, w.y, acc[1][1]);
        acc[1][2] = fmaf(x1, w.z, acc[1][2]); acc[1][3] = fmaf(x1, w.w, acc[1][3]);
        acc[2][0] = fmaf(x2, w.x, acc[2][0]); acc[2][1] = fmaf(x2, w.y, acc[2][1]);
        acc[2][2] = fmaf(x2, w.z, acc[2][2]); acc[2][3] = fmaf(x2, w.w, acc[2][3]);
        acc[3][0] = fmaf(x3, w.x, acc[3][0]); acc[3][1] = fmaf(x3, w.y, acc[3][1]);
        acc[3][2] = fmaf(x3, w.z, acc[3][2]); acc[3][3] = fmaf(x3, w.w, acc[3][3]);
    }

    float bia[4];
#pragma unroll
    for (int jj = 0; jj < 4; jj++) bia[jj] = bias[lane * 4 + jj];

#pragma unroll
    for (int rr = 0; rr < 4; rr++) {
        int row = rowbase + wid * 4 + rr;
        float v[4];
        if (mode == 0) {
            float mx = fmaxf(fmaxf(acc[rr][0], acc[rr][1]), fmaxf(acc[rr][2], acc[rr][3]));
#pragma unroll
            for (int o = 16; o; o >>= 1) mx = fmaxf(mx, __shfl_xor_sync(0xffffffffu, mx, o));
            float s = 0.f;
#pragma unroll
            for (int jj = 0; jj < 4; jj++) { v[jj] = __expf(acc[rr][jj] - mx); s += v[jj]; }
#pragma unroll
            for (int o = 16; o; o >>= 1) s += __shfl_xor_sync(0xffffffffu, s, o);
            float inv = 1.f / s;
#pragma unroll
            for (int jj = 0; jj < 4; jj++) v[jj] *= inv;
        } else if (mode == 1) {
#pragma unroll
            for (int jj = 0; jj < 4; jj++) v[jj] = acc[rr][jj] + bia[jj];
        } else if (mode == 2) {
#pragma unroll
            for (int jj = 0; jj < 4; jj++) v[jj] = 1.f / (1.f + __expf(-(acc[rr][jj] + bia[jj])));
        } else {
#pragma unroll
            for (int jj = 0; jj < 4; jj++) v[jj] = tanhf(acc[rr][jj] + bia[jj]);
        }
        if (row < nrows)
            *(float4*)(dst + (size_t)row * 128 + lane * 4) = make_float4(v[0], v[1], v[2], v[3]);
    }
}

// ============================================================
// Phase B: memory recurrence + Mv trajectory + rt partials.
// grid 512 = 64 b x 8 n-chunks, 128 threads.
// Warp covers the FULL 16-n chunk x 32 d:
//   lane = n4*8 + dq  ->  n-group n4 (4 n), d-quad dq  (d = wid*32 + dq*4)
// rt reduction over n is 2 shfl_xor stages INSIDE the warp:
// no smem exchange, NO __syncthreads in the step loop.
// ============================================================
__global__ void kB(const int* __restrict__ q, const int* __restrict__ r,
                   const float* __restrict__ Mv0, float* __restrict__ outMv) {
    __shared__ int sq[104], sr[104];
    const int blk = blockIdx.x;
    const int b = blk >> 3, chunk = blk & 7;
    const int tid = threadIdx.x;
    const int wid = tid >> 5, lane = tid & 31;
    const int n4 = lane >> 3;            // 0..3  (4 n each)
    const int d  = wid * 32 + (lane & 7) * 4;
    const int nbase = chunk * 16 + n4 * 4;

    // single-pass clamped fill of 101 entries (index 100 duplicates 99);
    // no cross-thread reads -> no race. 128 threads cover i=0..100 in one pass.
    for (int i = tid; i < 101; i += 128) {
        int j = i < 100 ? i : 99;
        sq[i] = q[b * 100 + j];
        sr[i] = r[b * 100 + j];
    }

    float4 M0 = *(const float4*)(Mv0 + (nbase + 0) * 128 + d);
    float4 M1 = *(const float4*)(Mv0 + (nbase + 1) * 128 + d);
    float4 M2 = *(const float4*)(Mv0 + (nbase + 2) * 128 + d);
    float4 M3 = *(const float4*)(Mv0 + (nbase + 3) * 128 + d);
    __syncthreads();   // one barrier total (sq/sr visibility)

    int qv = sq[0];
    int qr = qv + 1000 * sr[0];
    float4 wv = *(const float4*)(g_Wp + (size_t)qv * 128 + nbase);
    float4 ev = *(const float4*)(g_Ep + (size_t)qr * 128 + d);
    float4 av = *(const float4*)(g_Ap + (size_t)qr * 128 + d);

    for (int t = 0; t < 100; t++) {
        // prefetch next step's table rows (branchless via clamped sq/sr)
        const int qv2 = sq[t + 1];
        const int qr2 = qv2 + 1000 * sr[t + 1];
        float4 wv2 = *(const float4*)(g_Wp + (size_t)qv2 * 128 + nbase);
        float4 ev2 = *(const float4*)(g_Ep + (size_t)qr2 * 128 + d);
        float4 av2 = *(const float4*)(g_Ap + (size_t)qr2 * 128 + d);

        // rt partial from PRE-update M (sum over this thread's 4 n)
        float4 P;
        P.x = fmaf(wv.x, M0.x, fmaf(wv.y, M1.x, fmaf(wv.z, M2.x, wv.w * M3.x)));
        P.y = fmaf(wv.x, M0.y, fmaf(wv.y, M1.y, fmaf(wv.z, M2.y, wv.w * M3.y)));
        P.z = fmaf(wv.x, M0.z, fmaf(wv.y, M1.z, fmaf(wv.z, M2.z, wv.w * M3.z)));
        P.w = fmaf(wv.x, M0.w, fmaf(wv.y, M1.w, fmaf(wv.z, M2.w, wv.w * M3.w)));

        // reduce over the 4 n-groups (lanes xor 8, 16) -> full 16-n chunk sum
#pragma unroll
        for (int o = 8; o <= 16; o <<= 1) {
            P.x += __shfl_xor_sync(0xffffffffu, P.x, o);
            P.y += __shfl_xor_sync(0xffffffffu, P.y, o);
            P.z += __shfl_xor_sync(0xffffffffu, P.z, o);
            P.w += __shfl_xor_sync(0xffffffffu, P.w, o);
        }

        // update: M += w * (a - M*e)   (== M*(1-w*e) + w*a)
#define UPD(MM, WI) { \
        float ux = fmaf(-(MM).x, ev.x, av.x); (MM).x = fmaf((WI), ux, (MM).x); \
        float uy = fmaf(-(MM).y, ev.y, av.y); (MM).y = fmaf((WI), uy, (MM).y); \
        float uz = fmaf(-(MM).z, ev.z, av.z); (MM).z = fmaf((WI), uz, (MM).z); \
        float uw = fmaf(-(MM).w, ev.w, av.w); (MM).w = fmaf((WI), uw, (MM).w); }
        UPD(M0, wv.x); UPD(M1, wv.y); UPD(M2, wv.z); UPD(M3, wv.w);
#undef UPD

        const size_t rowb = (size_t)(t * 64 + b);
        float* o = outMv + (rowb * 128 + nbase) * 128 + d;
        *(float4*)(o)       = M0;
        *(float4*)(o + 128) = M1;
        *(float4*)(o + 256) = M2;
        *(float4*)(o + 384) = M3;

        if (n4 == 0)
            *(float4*)(g_R + (rowb * 8 + chunk) * 128 + d) = P;

        wv = wv2; ev = ev2; av = av2;
    }
}

// ============================================================
// Phase C: reduce rt partials, ft = tanh(rt@f_W0 + G), p = sigmoid(ft.p_W + p_b)
// grid 200 = 100 t x 2 b-halves, 256 threads (80KB smem -> 2 blocks/SM).
// Warp owns 4 b-rows; lane owns 4 cols.
// ============================================================
__global__ void kC(const int* __restrict__ q, const float* __restrict__ f_W,
                   const float* __restrict__ p_W, const float* __restrict__ p_b,
                   float* __restrict__ outP) {
    extern __shared__ float smc[];
    float* rts = smc;         // 32*128 = 16KB
    float* Ws  = smc + 4096;  // 128*128 = 64KB (f_W rows 0..127)
    const int t = blockIdx.x >> 1, half = blockIdx.x & 1;
    const int tid = threadIdx.x;
    const int bbase = half * 32;

    for (int i = tid; i < 4096; i += 256) {
        int bl = i >> 7, dd = i & 127;
        const float* rp = g_R + ((size_t)(t * 64 + bbase + bl) * 8) * 128 + dd;
        float s = rp[0];
#pragma unroll
        for (int c = 1; c < 8; c++) s += rp[c * 128];
        rts[i] = s;
    }
    for (int i = tid; i < 4096; i += 256)
        ((float4*)Ws)[i] = ((const float4*)f_W)[i];
    __syncthreads();

    const int wid = tid >> 5, lane = tid & 31;
    float acc[4][4];
#pragma unroll
    for (int rr = 0; rr < 4; rr++)
#pragma unroll
        for (int jj = 0; jj < 4; jj++) acc[rr][jj] = 0.f;

    const float* xrow = rts + (wid * 4) * 128;
#pragma unroll 4
    for (int k = 0; k < 128; k++) {
        float4 w = *(float4*)(Ws + k * 128 + lane * 4);
        float x0 = xrow[k], x1 = xrow[128 + k], x2 = xrow[256 + k], x3 = xrow[384 + k];
        acc[0][0] = fmaf(x0, w.x, acc[0][0]); acc[0][1] = fmaf(x0, w.y, acc[0][1]);
        acc[0][2] = fmaf(x0, w.z, acc[0][2]); acc[0][3] = fmaf(x0, w.w, acc[0][3]);
        acc[1][0] = fmaf(x1, w.x, acc[1][0]); acc[1][1] = fmaf(x1, w.y, acc[1][1]);
        acc[1][2] = fmaf(x1, w.z, acc[1][2]); acc[1][3] = fmaf(x1, w.w, acc[1][3]);
        acc[2][0] = fmaf(x2, w.x, acc[2][0]); acc[2][1] = fmaf(x2, w.y, acc[2][1]);
        acc[2][2] = fmaf(x2, w.z, acc[2][2]); acc[2][3] = fmaf(x2, w.w, acc[2][3]);
        acc[3][0] = fmaf(x3, w.x, acc[3][0]); acc[3][1] = fmaf(x3, w.y, acc[3][1]);
        acc[3][2] = fmaf(x3, w.z, acc[3][2]); acc[3][3] = fmaf(x3, w.w, acc[3][3]);
    }

    float pw[4];
#pragma unroll
    for (int jj = 0; jj < 4; jj++) pw[jj] = p_W[lane * 4 + jj];
    const float pb = p_b[0];

#pragma unroll
    for (int rr = 0; rr < 4; rr++) {
        int b = bbase + wid * 4 + rr;
        int qv = q[b * 100 + t];
        const float* Gr = g_Gp + (size_t)qv * 128 + lane * 4;
        float dot = 0.f;
#pragma unroll
        for (int jj = 0; jj < 4; jj++) {
            float h = acc[rr][jj] + Gr[jj];
            dot = fmaf(tanhf(h), pw[jj], dot);
        }
#pragma unroll
        for (int o = 16; o; o >>= 1) dot += __shfl_xor_sync(0xffffffffu, dot, o);
        if (lane == 0) outP[t * 64 + b] = 1.f / (1.f + __expf(-(dot + pb)));
    }
}

// ============================================================
extern "C" void kernel_launch(void* const* d_in, const int* in_sizes, int n_in,
                              void* d_out, int out_size) {
    const int*   q     = (const int*)d_in[0];
    const int*   r     = (const int*)d_in[1];
    const float* k_emb = (const float*)d_in[2];
    const float* v_emb = (const float*)d_in[3];
    const float* Mk    = (const float*)d_in[4];
    const float* Mv0   = (const float*)d_in[5];
    const float* f_W   = (const float*)d_in[6];
    const float* f_b   = (const float*)d_in[7];
    const float* p_W   = (const float*)d_in[8];
    const float* p_b   = (const float*)d_in[9];
    const float* e_W   = (const float*)d_in[10];
    const float* e_b   = (const float*)d_in[11];
    const float* a_W   = (const float*)d_in[12];
    const float* a_b   = (const float*)d_in[13];
    float* out = (float*)d_out;

    cudaFuncSetAttribute(kA, cudaFuncAttributeMaxDynamicSharedMemorySize, 81920);
    cudaFuncSetAttribute(kC, cudaFuncAttributeMaxDynamicSharedMemorySize, 81920);

    kA<<<190, 256, 81920>>>(k_emb, v_emb, Mk, f_W, f_b, e_W, e_b, a_W, a_b);
    kB<<<512, 128>>>(q, r, Mv0, out + 6400);
    kC<<<200, 256, 81920>>>(q, f_W, p_W, p_b, out);
}